// round 17
// baseline (speedup 1.0000x reference)
#include <cuda_runtime.h>
#include <cuda_fp16.h>
#include <stdint.h>
#include <math.h>

#define B_ 64
#define K_ 8
#define T_ 12
#define H_ 2048
#define IN_ 2048
#define D_ 400
#define E_ 128
#define BK_ 512
#define G4H_ 8192
#define LDIH_ 4224
#define KM1_ 7
#define NHH_ ((size_t)BK_*H_)

__device__ float d_Zpre[T_*BK_*G4H_];
__device__ float d_Emb[T_*BK_*E_];
__device__ float d_ZxB[B_*G4H_];
__device__ float d_logpart[8*BK_*D_];
__device__ float d_Z[BK_*G4H_];
__device__ float d_c2[2][BK_*H_];
__device__ float d_hd[BK_*H_];
__device__ float d_lpt[BK_*D_];
__device__ float d_gm[BK_*D_];
__device__ float d_G[2][BK_];
__device__ float d_logp[2][BK_];
__device__ float d_samp[2][BK_*T_];
__device__ float d_outs[2][BK_*T_];
__device__ float d_ent[B_];
__device__ float d_wpq[B_*KM1_];
__device__ float d_lgp[B_*KM1_];
__device__ int d_greedy[BK_];
__device__ int d_order[BK_];
__device__ int d_idxk[B_*K_];
__device__ float d_gval[B_*K_];

// fp16 h/m planes (2 stacked copies each; m = v - h)
__device__ __half sWih[2ull*G4H_*LDIH_];
__device__ __half sWhh[2ull*G4H_*H_];
__device__ __half sWfc1[2ull*H_*H_];
__device__ __half sWout[2ull*D_*H_];
__device__ __half sX3[2ull*T_*BK_*IN_];
__device__ __half sEmb[2ull*T_*BK_*E_];
__device__ __half sXf[2ull*B_*IN_];
__device__ __half sH2[2ull*BK_*H_];
__device__ __half sHd[2ull*BK_*H_];

__device__ __forceinline__ float sigf(float x) { return 1.f / (1.f + expf(-x)); }
__device__ __forceinline__ unsigned orderf(float f) {
    unsigned u = __float_as_uint(f);
    return (u & 0x80000000u) ? ~u : (u | 0x80000000u);
}
__device__ __forceinline__ float unorderf(unsigned e) {
    unsigned b = (e & 0x80000000u) ? (e ^ 0x80000000u) : ~e;
    return __uint_as_float(b);
}
__device__ __forceinline__ uint32_t smem_u32(const void* p) {
    uint32_t a;
    asm("{ .reg .u64 t; cvta.to.shared.u64 t, %1; cvt.u32.u64 %0, t; }" : "=r"(a) : "l"(p));
    return a;
}
__device__ __forceinline__ void ldm4(uint32_t* r, uint32_t addr) {
    asm volatile("ldmatrix.sync.aligned.m8n8.x4.shared.b16 {%0,%1,%2,%3}, [%4];"
        : "=r"(r[0]), "=r"(r[1]), "=r"(r[2]), "=r"(r[3]) : "r"(addr));
}
__device__ __forceinline__ void mma16816(float* c, const uint32_t* a, const uint32_t* b) {
    asm volatile("mma.sync.aligned.m16n8k16.row.col.f32.f16.f16.f32 "
        "{%0,%1,%2,%3}, {%4,%5,%6,%7}, {%8,%9}, {%0,%1,%2,%3};"
        : "+f"(c[0]), "+f"(c[1]), "+f"(c[2]), "+f"(c[3])
        : "r"(a[0]), "r"(a[1]), "r"(a[2]), "r"(a[3]), "r"(b[0]), "r"(b[1]));
}
__device__ __forceinline__ void cpa16(uint32_t dst, const void* src, int sz) {
    asm volatile("cp.async.ca.shared.global [%0], [%1], 16, %2;" :: "r"(dst), "l"(src), "r"(sz) : "memory");
}
__device__ __forceinline__ void wsplit2(__half* base, size_t plane, size_t i, float v) {
    __half h = __float2half(v);
    base[i] = h;
    base[plane + i] = __float2half(v - __half2float(h));
}

// =====================================================================
// Fused fp16 split HMMA GEMM: acc = A_h B_h + A_h B_m + A_m B_h.
// Tile BM x 256, BK=64, 256 threads (8 warps, warp tile (BM/2) x 64).
// rowmap: optional A-row indirection (beam gather fused into staging).
// kchunk != 0: split-K over gridDim.z, partials stacked in C.
// =====================================================================
template<int BM>
__global__ __launch_bounds__(256)
void gemm_hmma(const __half* A, size_t Asz, int lda, const int* rowmap,
               const __half* Bm, size_t Bsz, int ldb, int kbB,
               const float* Cin, const float* bias, const float* bias2, const float* zxb,
               float* C, int ldc, int M, int N, int K, int do_relu, int kchunk)
{
    extern __shared__ char smem[];
    constexpr int MI = BM / 32;
    constexpr int APB = BM * 128;
    constexpr int BPB = 32768;
    constexpr int CHB = 2*APB + 2*BPB;

    if (kchunk) {
        int kz = blockIdx.z;
        A += (size_t)kz * kchunk;
        kbB += kz * kchunk;
        C += (size_t)kz * M * ldc;
        K = kchunk;
    }
    const int tid = threadIdx.x;
    const int wid = tid >> 5;
    const int lane = tid & 31;
    const int bm = blockIdx.y * BM;
    const int bn = blockIdx.x * 256;
    const int wm = (wid & 1) * (BM / 2);
    const int wn = (wid >> 1) * 64;
    const uint32_t sbase = smem_u32(smem);

    float acc[MI][8][4];
#pragma unroll
    for (int i = 0; i < MI; i++)
#pragma unroll
        for (int j = 0; j < 8; j++)
#pragma unroll
            for (int e = 0; e < 4; e++) acc[i][j][e] = 0.f;

    const int NC = K >> 6;

    auto stage_async = [&](int kc, int buf) {
        int ka = kc * 64;
        int kb = kbB + kc * 64;
        uint32_t base = sbase + buf * CHB;
#pragma unroll
        for (int pl = 0; pl < 2; pl++) {
            const __half* Ap = A + (size_t)pl * Asz;
            uint32_t Ad = base + pl * APB;
#pragma unroll
            for (int i = 0; i < BM/32; i++) {
                int idx = tid + i * 256;
                int r = idx >> 3;
                int cb = (idx & 7) << 4;
                int gr = bm + r;
                int ok = (gr < M);
                if (ok && rowmap) gr = rowmap[gr];
                const char* g = ok ? (const char*)(Ap + (size_t)gr * lda + ka) + cb
                                   : (const char*)Ap;
                cpa16(Ad + r * 128 + (cb ^ ((r & 7) * 16)), g, ok ? 16 : 0);
            }
        }
#pragma unroll
        for (int pl = 0; pl < 2; pl++) {
            const __half* Bp = Bm + (size_t)pl * Bsz;
            uint32_t Bd = base + 2*APB + pl * BPB;
#pragma unroll
            for (int i = 0; i < 8; i++) {
                int idx = tid + i * 256;
                int r = idx >> 3;
                int cb = (idx & 7) << 4;
                int ok = (bn + r < N);
                const char* g = ok ? (const char*)(Bp + (size_t)(bn + r) * ldb + kb) + cb
                                   : (const char*)Bp;
                cpa16(Bd + r * 128 + (cb ^ ((r & 7) * 16)), g, ok ? 16 : 0);
            }
        }
        asm volatile("cp.async.commit_group;" ::: "memory");
    };

    auto compute = [&](int buf) {
        uint32_t base = sbase + buf * CHB;
#pragma unroll
        for (int kk = 0; kk < 4; kk++) {
            uint32_t afh[MI][4], afm[MI][4];
            {
                int ro = ((lane >> 3) & 1) * 8 + (lane & 7);
                int co = kk * 32 + ((lane >> 4) & 1) * 16;
#pragma unroll
                for (int i = 0; i < MI; i++) {
                    int r = wm + i * 16 + ro;
                    uint32_t off = r * 128 + (co ^ ((r & 7) * 16));
                    ldm4(afh[i], base + off);
                    ldm4(afm[i], base + APB + off);
                }
            }
            uint32_t bfh[8][2], bfm[8][2];
            {
                int ro = ((lane >> 4) & 1) * 8 + (lane & 7);
                int co = kk * 32 + ((lane >> 3) & 1) * 16;
#pragma unroll
                for (int j2 = 0; j2 < 4; j2++) {
                    int r = wn + j2 * 16 + ro;
                    uint32_t off = r * 128 + (co ^ ((r & 7) * 16));
                    uint32_t t4[4];
                    ldm4(t4, base + 2*APB + off);
                    bfh[j2*2][0] = t4[0]; bfh[j2*2][1] = t4[1];
                    bfh[j2*2+1][0] = t4[2]; bfh[j2*2+1][1] = t4[3];
                    ldm4(t4, base + 2*APB + BPB + off);
                    bfm[j2*2][0] = t4[0]; bfm[j2*2][1] = t4[1];
                    bfm[j2*2+1][0] = t4[2]; bfm[j2*2+1][1] = t4[3];
                }
            }
#pragma unroll
            for (int i = 0; i < MI; i++)
#pragma unroll
                for (int j = 0; j < 8; j++) {
                    mma16816(acc[i][j], afh[i], bfh[j]);
                    mma16816(acc[i][j], afh[i], bfm[j]);
                    mma16816(acc[i][j], afm[i], bfh[j]);
                }
        }
    };

    stage_async(0, 0);
    asm volatile("cp.async.wait_group 0;" ::: "memory");
    __syncthreads();
    for (int c = 0; c < NC; c++) {
        if (c + 1 < NC) stage_async(c + 1, (c + 1) & 1);
        compute(c & 1);
        if (c + 1 < NC) asm volatile("cp.async.wait_group 0;" ::: "memory");
        __syncthreads();
    }

#pragma unroll
    for (int i = 0; i < MI; i++) {
#pragma unroll
        for (int j = 0; j < 8; j++) {
            int r0 = bm + wm + i * 16 + (lane >> 2);
            int c0 = bn + wn + j * 8 + (lane & 3) * 2;
#pragma unroll
            for (int e = 0; e < 4; e++) {
                int m = r0 + (e >> 1) * 8;
                int n = c0 + (e & 1);
                if (m >= M || n >= N) continue;
                float v = acc[i][j][e];
                if (Cin) v += Cin[(size_t)m * ldc + n];
                if (bias) v += bias[n];
                if (bias2) v += bias2[n];
                if (zxb) v += zxb[(size_t)(m & 63) * ldc + n];
                if (do_relu) v = fmaxf(v, 0.f);
                C[(size_t)m * ldc + n] = v;
            }
        }
    }
}

__global__ void split2(const float* in, __half* out, size_t n) {
    size_t i = (size_t)blockIdx.x * blockDim.x + threadIdx.x;
    if (i >= n) return;
    wsplit2(out, n, i, in[i]);
}

__global__ void reduce_k(const float* parts, int nparts, int total, int ncols,
                         const float* bias, float* out, int do_relu, __half* bout) {
    int i = blockIdx.x * blockDim.x + threadIdx.x;
    if (i >= total) return;
    float s = 0.f;
    for (int p = 0; p < nparts; p++) s += parts[(size_t)p * total + i];
    if (bias) s += bias[i % ncols];
    if (do_relu) s = fmaxf(s, 0.f);
    out[i] = s;
    if (bout) wsplit2(bout, (size_t)total, (size_t)i, s);
}

__global__ void zero_init() {
    int i = blockIdx.x * blockDim.x + threadIdx.x;
    if (i < BK_) { d_G[0][i] = 0.f; d_logp[0][i] = 0.f; }
    if (i < BK_*T_) { d_samp[0][i] = 0.f; d_outs[0][i] = 0.f; }
    if (i < B_) d_ent[i] = 0.f;
}

__global__ void emb_kernel(const int* pop_all, const float* W_emb, const float* b_emb) {
    int i = blockIdx.x * blockDim.x + threadIdx.x;
    if (i >= T_*BK_*E_) return;
    int row = i >> 7;
    int e = i & 127;
    int p = pop_all[row];
    d_Emb[i] = fmaxf(W_emb[e*D_ + p] + b_emb[e], 0.f);
}

// LSTM pointwise with fused c-gather (order from step t-1); writes c2[t&1] + sH2 planes
__global__ void lstm_pw(const float* zsrc, int t) {
    int i = blockIdx.x * blockDim.x + threadIdx.x;
    if (i >= BK_*H_) return;
    int bk = i >> 11;
    int col = i & 2047;
    const float* zr = zsrc + (size_t)bk * G4H_;
    float cprev = 0.f;
    if (t > 0) {
        int o = d_order[bk];
        cprev = d_c2[(t - 1) & 1][o*H_ + col];
    }
    float cn = sigf(zr[H_ + col]) * cprev + sigf(zr[col]) * tanhf(zr[2*H_ + col]);
    d_c2[t & 1][i] = cn;
    float hv = sigf(zr[3*H_ + col]) * tanhf(cn);
    wsplit2(sH2, NHH_, (size_t)i, hv);
}

// fused: logits split-K reduce + masked log_softmax + greedy + (t>0) gumbel g
__global__ void softmax_kernel(const int* pop_t, const float* mask, const float* u_t,
                               const float* b_out, int t, int src) {
    int bk = blockIdx.x;
    int tid = threadIdx.x;
    __shared__ float sm[D_];
    __shared__ float red[128];
    __shared__ unsigned long long redu[128];
    const float* mrow = mask + (size_t)pop_t[bk] * D_;
    float NEG_INF = __int_as_float(0xff800000);
    float lmax = NEG_INF;
    for (int d = tid; d < D_; d += 128) {
        float s = 0.f;
#pragma unroll
        for (int p = 0; p < 8; p++) s += d_logpart[(size_t)p * BK_ * D_ + bk * D_ + d];
        float v = s + b_out[d] + mrow[d];
        sm[d] = v;
        lmax = fmaxf(lmax, v);
    }
    red[tid] = lmax; __syncthreads();
    for (int s = 64; s > 0; s >>= 1) { if (tid < s) red[tid] = fmaxf(red[tid], red[tid+s]); __syncthreads(); }
    float M = red[0]; __syncthreads();
    float ssum = 0.f;
    for (int d = tid; d < D_; d += 128) ssum += expf(sm[d] - M);
    red[tid] = ssum; __syncthreads();
    for (int s = 64; s > 0; s >>= 1) { if (tid < s) red[tid] += red[tid+s]; __syncthreads(); }
    float logZ = M + logf(red[0]);
    unsigned long long bkey = 0ull;
    for (int d = tid; d < D_; d += 128) {
        unsigned long long key = ((unsigned long long)orderf(sm[d]) << 32) | (unsigned)(0xFFFFFFFFu - d);
        bkey = bkey > key ? bkey : key;
    }
    redu[tid] = bkey; __syncthreads();
    for (int s = 64; s > 0; s >>= 1) { if (tid < s) redu[tid] = redu[tid] > redu[tid+s] ? redu[tid] : redu[tid+s]; __syncthreads(); }
    if (tid == 0) d_greedy[bk] = (int)(0xFFFFFFFFu - (unsigned)(redu[0] & 0xFFFFFFFFu));
    for (int d = tid; d < D_; d += 128) d_lpt[bk*D_ + d] = sm[d] - logZ;
    if (t > 0) {
        float lpc = d_logp[src][bk];
        float Gc = d_G[src][bk];
        __syncthreads();
        for (int d = tid; d < D_; d += 128) {
            float uu = fminf(fmaxf(u_t[bk*D_ + d], 1e-9f), 1.f - 1e-9f);
            sm[d] = (sm[d] - logZ) + lpc + (-logf(-logf(uu)));
        }
        __syncthreads();
        float m2 = NEG_INF;
        for (int d = tid; d < D_; d += 128) m2 = fmaxf(m2, sm[d]);
        red[tid] = m2; __syncthreads();
        for (int s = 64; s > 0; s >>= 1) { if (tid < s) red[tid] = fmaxf(red[tid], red[tid+s]); __syncthreads(); }
        float Zm = red[0];
        for (int d = tid; d < D_; d += 128) {
            float gp = sm[d];
            float v = Gc - gp + log1pf(-expf(gp - Zm));
            d_gm[bk*D_ + d] = Gc - fmaxf(v, 0.f) - log1pf(expf(-fabsf(v)));
        }
    }
}

// top-8 per image + fused beam update (t > 0 path)
__global__ void topk_kernel(int t, int src) {
    int b = blockIdx.x;
    int tid = threadIdx.x;
    __shared__ unsigned long long red[128];
    __shared__ unsigned long long picked[K_];
    for (int it = 0; it < K_; it++) {
        unsigned long long best = 0ull;
        for (int cidx = tid; cidx < K_*D_; cidx += 128) {
            int k = cidx / D_;
            int d = cidx - k*D_;
            float v = d_gm[(k*B_ + b)*D_ + d];
            unsigned long long key = ((unsigned long long)orderf(v) << 32) | (unsigned)(0xFFFFFFFFu - cidx);
            bool skip = false;
            for (int j = 0; j < it; j++) { if (picked[j] == key) skip = true; }
            if (!skip) best = best > key ? best : key;
        }
        red[tid] = best; __syncthreads();
        for (int s = 64; s > 0; s >>= 1) { if (tid < s) red[tid] = red[tid] > red[tid+s] ? red[tid] : red[tid+s]; __syncthreads(); }
        if (tid == 0) {
            unsigned long long w = red[0];
            picked[it] = w;
            d_idxk[b*K_ + it] = (int)(0xFFFFFFFFu - (unsigned)(w & 0xFFFFFFFFu));
            d_gval[b*K_ + it] = unorderf((unsigned)(w >> 32));
        }
        __syncthreads();
    }
    // fused beam update for this image's 8 beams
    if (tid < K_) {
        int k = tid;
        int bk = k*B_ + b;
        int dst = src ^ 1;
        int cidx = d_idxk[b*K_ + k];
        int ks = cidx / D_;
        int sample = cidx - ks*D_;
        int order = ks*B_ + b;
        float sel = d_lpt[order*D_ + sample];
        d_G[dst][bk] = d_gval[b*K_ + k];
        d_logp[dst][bk] = d_logp[src][order] + sel;
        d_order[bk] = order;
        for (int tt = 0; tt < T_; tt++) {
            d_samp[dst][bk*T_ + tt] = d_samp[src][order*T_ + tt];
            d_outs[dst][bk*T_ + tt] = d_outs[src][order*T_ + tt];
        }
        d_samp[dst][bk*T_ + t] = (float)sample;
        d_outs[dst][bk*T_ + t] = sel;
    }
}

// t == 0 beam update (greedy, identity order)
__global__ void beam0_kernel() {
    int bk = threadIdx.x;
    int sample = d_greedy[bk];
    float sel = d_lpt[bk*D_ + sample];
    d_G[1][bk] = d_G[0][bk];
    d_logp[1][bk] = d_logp[0][bk];
    d_order[bk] = bk;
    for (int tt = 0; tt < T_; tt++) {
        d_samp[1][bk*T_ + tt] = d_samp[0][bk*T_ + tt];
        d_outs[1][bk*T_ + tt] = d_outs[0][bk*T_ + tt];
    }
    d_samp[1][bk*T_ + 0] = (float)sample;
    d_outs[1][bk*T_ + 0] = sel;
}

// fused entropy + importance weights: one block per image
__global__ void entwq_kernel(const int* pop_t, const float* mask, int dst) {
    int b = blockIdx.x;
    int warp = threadIdx.x >> 5;
    int lane = threadIdx.x & 31;
    __shared__ float ent_s[KM1_];
    if (warp < KM1_) {
        int o = d_order[warp*B_ + b];
        const float* lpr = d_lpt + o*D_;
        const float* mrow = mask + (size_t)pop_t[o] * D_;
        float s = 0.f;
        for (int d = lane; d < D_; d += 32) {
            float lp = lpr[d];
            if (mrow[d] == 0.f) s += lp * expf(lp);
        }
        for (int off = 16; off; off >>= 1) s += __shfl_down_sync(0xffffffffu, s, off);
        if (lane == 0) ent_s[warp] = s;
    }
    __syncthreads();
    if (threadIdx.x == 0) {
        float gk = d_gval[b*K_ + (K_-1)];
        float wsum = 0.f;
        float upd = 0.f;
        for (int k = 0; k < KM1_; k++) {
            float phi = d_logp[dst][k*B_ + b];
            float x = gk - phi;
            float gls;
            if (x >= 10.f) { float y = expf(-x); gls = -x - 0.5f*y + y*y*(1.f/24.f); }
            else gls = logf(-expm1f(-expf(-x)));
            float w = expf(phi - gls);
            d_wpq[b*KM1_ + k] = w;
            d_lgp[b*KM1_ + k] = phi;
            wsum += w;
            upd += w * ent_s[k];
        }
        d_ent[b] += upd / wsum;
    }
}

__global__ void epilogue(float* out) {
    int i = blockIdx.x * blockDim.x + threadIdx.x;
    if (i >= 11712) return;
    if (i < 5376) {
        int b = i / 84;
        int r = i % 84;
        out[i] = d_outs[0][((r / T_)*B_ + b)*T_ + (r % T_)];
    } else if (i < 10752) {
        int q = i - 5376;
        int b = q / 84;
        int r = q % 84;
        out[i] = d_samp[0][((r / T_)*B_ + b)*T_ + (r % T_)];
    } else if (i < 10816) out[i] = d_ent[i - 10752];
    else if (i < 11264) out[i] = d_wpq[i - 10816];
    else out[i] = d_lgp[i - 11264];
}

#define SMEM128 196608
#define SMEM64 163840
#define FNIL (const float*)0
#define HNIL (__half*)0
#define INIL (const int*)0

extern "C" void kernel_launch(void* const* d_in, const int* in_sizes, int n_in,
                              void* d_out, int out_size)
{
    const float* x_f = (const float*)d_in[0];
    const float* x_f3 = (const float*)d_in[1];
    const float* gum_u = (const float*)d_in[2];
    const int* pop = (const int*)d_in[3];
    const float* mask = (const float*)d_in[4];
    const float* W_emb = (const float*)d_in[5];
    const float* b_emb = (const float*)d_in[6];
    const float* W_ih = (const float*)d_in[7];
    const float* W_hh = (const float*)d_in[8];
    const float* b_ih = (const float*)d_in[9];
    const float* b_hh = (const float*)d_in[10];
    const float* W_fc1 = (const float*)d_in[11];
    const float* b_fc1 = (const float*)d_in[12];
    const float* W_out = (const float*)d_in[13];
    const float* b_out = (const float*)d_in[14];

    float* pZpre;
    float* pEmb;
    float* pZxB;
    float* pZ;
    float* phd;
    float* plogp;
    int* porder;
    cudaGetSymbolAddress((void**)&pZpre, d_Zpre);
    cudaGetSymbolAddress((void**)&pEmb, d_Emb);
    cudaGetSymbolAddress((void**)&pZxB, d_ZxB);
    cudaGetSymbolAddress((void**)&pZ, d_Z);
    cudaGetSymbolAddress((void**)&phd, d_hd);
    cudaGetSymbolAddress((void**)&plogp, d_logpart);
    cudaGetSymbolAddress((void**)&porder, d_order);
    __half* pWih;
    __half* pWhh;
    __half* pWfc1;
    __half* pWout;
    __half* pX3;
    __half* pSEmb;
    __half* pXf;
    __half* pH2;
    __half* pHd;
    cudaGetSymbolAddress((void**)&pWih, sWih);
    cudaGetSymbolAddress((void**)&pWhh, sWhh);
    cudaGetSymbolAddress((void**)&pWfc1, sWfc1);
    cudaGetSymbolAddress((void**)&pWout, sWout);
    cudaGetSymbolAddress((void**)&pX3, sX3);
    cudaGetSymbolAddress((void**)&pSEmb, sEmb);
    cudaGetSymbolAddress((void**)&pXf, sXf);
    cudaGetSymbolAddress((void**)&pH2, sH2);
    cudaGetSymbolAddress((void**)&pHd, sHd);

    cudaFuncSetAttribute(gemm_hmma<128>, cudaFuncAttributeMaxDynamicSharedMemorySize, SMEM128);
    cudaFuncSetAttribute(gemm_hmma<64>, cudaFuncAttributeMaxDynamicSharedMemorySize, SMEM64);

    size_t nWih = (size_t)G4H_*LDIH_;
    size_t nWhh = (size_t)G4H_*H_;
    size_t nWfc1 = (size_t)H_*H_;
    size_t nWout = (size_t)D_*H_;
    size_t nX3 = (size_t)T_*BK_*IN_;
    size_t nEmb = (size_t)T_*BK_*E_;
    size_t nXf = (size_t)B_*IN_;

    // launches 1-4, then launch 5 = the dominant Zpre GEMM (ncu -s 5 hits it)
    zero_init<<<(BK_*T_ + 255)/256, 256>>>();
    emb_kernel<<<(T_*BK_*E_ + 255)/256, 256>>>(pop, W_emb, b_emb);
    split2<<<(unsigned)((nWih + 255)/256), 256>>>(W_ih, pWih, nWih);
    split2<<<(unsigned)((nX3 + 255)/256), 256>>>(x_f3, pX3, nX3);

    // Zpre = x_f3 @ W_ih[:, IN+E:].T  [6144, 8192], K=2048   (writes first)
    gemm_hmma<128><<<dim3(G4H_/256, T_*BK_/128), 256, SMEM128>>>(
        pX3, nX3, IN_, INIL, pWih, nWih, LDIH_, IN_ + E_,
        FNIL, FNIL, FNIL, FNIL,
        pZpre, G4H_, T_*BK_, G4H_, IN_, 0, 0);

    split2<<<(unsigned)((nWhh + 255)/256), 256>>>(W_hh, pWhh, nWhh);
    split2<<<(unsigned)((nWfc1 + 255)/256), 256>>>(W_fc1, pWfc1, nWfc1);
    split2<<<(unsigned)((nWout + 255)/256), 256>>>(W_out, pWout, nWout);
    split2<<<(unsigned)((nEmb + 255)/256), 256>>>(pEmb, pSEmb, nEmb);
    split2<<<(unsigned)((nXf + 255)/256), 256>>>(x_f, pXf, nXf);

    // ZxB = x_f @ W_ih[:, :IN].T  [64, 8192], split-K 4 (parts in d_Z)
    gemm_hmma<64><<<dim3(G4H_/256, 1, 4), 256, SMEM64>>>(
        pXf, nXf, IN_, INIL, pWih, nWih, LDIH_, 0,
        FNIL, FNIL, FNIL, FNIL,
        pZ, G4H_, B_, G4H_, IN_, 0, 512);
    reduce_k<<<(B_*G4H_ + 255)/256, 256>>>(pZ, 4, B_*G4H_, G4H_, FNIL, pZxB, 0, HNIL);

    // Zpre += Emb @ W_ih[:, IN:IN+E].T + b_ih + b_hh + ZxB[b]  [6144, 8192], K=128
    gemm_hmma<128><<<dim3(G4H_/256, T_*BK_/128), 256, SMEM128>>>(
        pSEmb, nEmb, E_, INIL, pWih, nWih, LDIH_, IN_,
        pZpre, b_ih, b_hh, pZxB,
        pZpre, G4H_, T_*BK_, G4H_, E_, 0, 0);

    for (int t = 0; t < T_; t++) {
        int src = t & 1;
        const float* zsrc = pZpre + (size_t)t*BK_*G4H_;
        if (t > 0) {
            // Z = h_prev[order] @ W_hh.T + Zpre[t]  (gather fused via rowmap)
            gemm_hmma<128><<<dim3(G4H_/256, BK_/128), 256, SMEM128>>>(
                pH2, NHH_, H_, porder, pWhh, nWhh, H_, 0,
                zsrc, FNIL, FNIL, FNIL,
                pZ, G4H_, BK_, G4H_, H_, 0, 0);
            zsrc = pZ;
        }
        lstm_pw<<<(BK_*H_ + 255)/256, 256>>>(zsrc, t);
        // fc1: split-K 2, reduce applies bias+relu and emits sHd planes
        gemm_hmma<64><<<dim3(H_/256, BK_/64, 2), 256, SMEM64>>>(
            pH2, NHH_, H_, INIL, pWfc1, nWfc1, H_, 0,
            FNIL, FNIL, FNIL, FNIL,
            pZ, H_, BK_, H_, H_, 0, 1024);
        reduce_k<<<(BK_*H_ + 255)/256, 256>>>(pZ, 2, BK_*H_, H_, b_fc1, phd, 1, pHd);
        // logits: split-K 8 (reduce fused into softmax)
        gemm_hmma<64><<<dim3(2, BK_/64, 8), 256, SMEM64>>>(
            pHd, NHH_, H_, INIL, pWout, nWout, H_, 0,
            FNIL, FNIL, FNIL, FNIL,
            plogp, D_, BK_, D_, H_, 0, 256);

        softmax_kernel<<<BK_, 128>>>(pop + t*BK_, mask, gum_u + (size_t)t*BK_*D_, b_out, t, src);
        if (t == 0) beam0_kernel<<<1, BK_>>>();
        else topk_kernel<<<B_, 128>>>(t, src);
        if (t > 0) entwq_kernel<<<B_, 256>>>(pop + t*BK_, mask, src ^ 1);
    }
    epilogue<<<(11712 + 255)/256, 256>>>((float*)d_out);
}